// round 3
// baseline (speedup 1.0000x reference)
#include <cuda_runtime.h>
#include <cuda_fp16.h>
#include <math.h>

#define HF 200
#define WF 200
#define CH 256
#define HO 7
#define WO 7
#define SUBS 2
#define HS (HO * SUBS)   // 14
#define WS (WO * SUBS)   // 14

// Channels-last fp16 scratch copy: g_featTh[(y*WF + x)*CH + c]  (20.5 MB)
__device__ __align__(16) __half g_featTh[HF * WF * CH];

static __device__ __forceinline__ __half2 u2h2(unsigned u) {
    return *reinterpret_cast<__half2*>(&u);
}

// ---------------------------------------------------------------------------
// Kernel 1: transpose (C, H*W) f32 -> (H*W, C) fp16 via 32x32 smem tiles
// (measured at ~7 TB/s: HBM-roofline bound, unchanged)
// ---------------------------------------------------------------------------
__global__ void transpose_kernel(const float* __restrict__ in) {
    __shared__ float tile[32][33];
    const int p0 = blockIdx.x * 32;
    const int c0 = blockIdx.y * 32;
    const int tx = threadIdx.x;
    const int ty = threadIdx.y;

#pragma unroll
    for (int i = 0; i < 32; i += 8) {
        tile[ty + i][tx] = in[(size_t)(c0 + ty + i) * (HF * WF) + (p0 + tx)];
    }
    __syncthreads();

    const int tid = ty * 32 + tx;
#pragma unroll
    for (int it = 0; it < 2; it++) {
        const int idx = tid + it * 256;
        const int p_local = idx >> 4;
        const int k = idx & 15;
        __half2 h = __floats2half2_rn(tile[2 * k][p_local], tile[2 * k + 1][p_local]);
        *(__half2*)&g_featTh[(size_t)(p0 + p_local) * CH + c0 + 2 * k] = h;
    }
}

// ---------------------------------------------------------------------------
// Kernel 2: ROI align + 2x2 max subsample.
// Grid: (N, HO). Block: 256 threads; 224 active = 7 pw x 32 c8 chunks.
// Setup threads precompute per-sample corner BYTE offsets (uint4) and
// half2-packed fx/fy into smem; main loop is pure LDS -> LDG.128 -> HFMA2.
// ---------------------------------------------------------------------------
__global__ __launch_bounds__(256) void roialign_kernel(
    const float* __restrict__ rois,
    const float* __restrict__ img_size,
    float* __restrict__ out)
{
    const int n  = blockIdx.x;
    const int ph = blockIdx.y;
    const int tid = threadIdx.x;

    __shared__ float   s_out[WO][CH + 4];
    __shared__ uint4   s_off[2 * WS];     // [sy*14 + xs] -> (ul, ur, dl, dr) byte offsets
    __shared__ __half2 s_fx2[WS];
    __shared__ __half2 s_fy2[2];

    // --- per-ROI geometry (scalar, all threads) ---
    const float y1 = rois[n * 4 + 0];
    const float x1 = rois[n * 4 + 1];
    const float y2 = rois[n * 4 + 2];
    const float x2 = rois[n * 4 + 3];
    const float Hi = img_size[0];
    const float Wi = img_size[1];
    const float sy_scale = (HF - 1.0f) / (Hi - 1.0f);
    const float sx_scale = (WF - 1.0f) / (Wi - 1.0f);
    const float r0 = y1 * sy_scale;
    const float r1 = x1 * sx_scale;
    const float h_step = (y2 * sy_scale - r0) / (float)HS;
    const float w_step = (x2 * sx_scale - r1) / (float)WS;

    // --- setup: 28 threads compute per-sample offsets + fractions ---
    if (tid < 2 * WS) {
        const int sy = (tid >= WS) ? 1 : 0;
        const int xs = tid - sy * WS;

        const float yy = ((float)(ph * SUBS + sy) + 0.5f) * h_step + r0;
        const float yf = floorf(yy);
        const int iu  = (int)yf;
        const int idn = (int)ceilf(yy);
        const float fy = yy - yf;

        const float xx = ((float)xs + 0.5f) * w_step + r1;
        const float xf = floorf(xx);
        const int il = (int)xf;
        const int ir = (int)ceilf(xx);
        const float fx = xx - xf;

        const unsigned rowu = (unsigned)(iu  * WF) * (CH * 2u);
        const unsigned rowd = (unsigned)(idn * WF) * (CH * 2u);
        const unsigned coll = (unsigned)il * (CH * 2u);
        const unsigned colr = (unsigned)ir * (CH * 2u);
        s_off[tid] = make_uint4(rowu + coll, rowu + colr, rowd + coll, rowd + colr);

        if (sy == 0) s_fx2[xs] = __float2half2_rn(fx);
        if (xs == 0) s_fy2[sy] = __float2half2_rn(fy);
    }
    __syncthreads();

    // --- main: 224 threads, fully unrolled 4 samples x 4 corners ---
    if (tid < WO * (CH / 8)) {
        const int pw = tid >> 5;         // output col
        const int c8 = tid & 31;         // 8-channel chunk
        const char* fb = (const char*)g_featTh + c8 * 16;

        __half2 best[4];
        const __half2 ninf = __float2half2_rn(-60000.0f);
#pragma unroll
        for (int j = 0; j < 4; j++) best[j] = ninf;

#pragma unroll
        for (int sy = 0; sy < SUBS; sy++) {
            const __half2 fy2 = s_fy2[sy];
#pragma unroll
            for (int sx = 0; sx < SUBS; sx++) {
                const int xs = pw * SUBS + sx;
                const uint4   o   = s_off[sy * WS + xs];
                const __half2 fx2 = s_fx2[xs];

                const uint4 hul = *(const uint4*)(fb + o.x);
                const uint4 hur = *(const uint4*)(fb + o.y);
                const uint4 hdl = *(const uint4*)(fb + o.z);
                const uint4 hdr = *(const uint4*)(fb + o.w);

                const unsigned* pul = (const unsigned*)&hul;
                const unsigned* pur = (const unsigned*)&hur;
                const unsigned* pdl = (const unsigned*)&hdl;
                const unsigned* pdr = (const unsigned*)&hdr;

#pragma unroll
                for (int j = 0; j < 4; j++) {
                    const __half2 ul = u2h2(pul[j]);
                    const __half2 ur = u2h2(pur[j]);
                    const __half2 dl = u2h2(pdl[j]);
                    const __half2 dr = u2h2(pdr[j]);
                    const __half2 t = __hfma2(fx2, __hsub2(ur, ul), ul);
                    const __half2 b = __hfma2(fx2, __hsub2(dr, dl), dl);
                    const __half2 v = __hfma2(fy2, __hsub2(b, t), t);
                    best[j] = __hmax2(best[j], v);
                }
            }
        }

        const int c = c8 * 8;
#pragma unroll
        for (int j = 0; j < 4; j++) {
            const float2 f = __half22float2(best[j]);
            s_out[pw][c + 2 * j + 0] = f.x;
            s_out[pw][c + 2 * j + 1] = f.y;
        }
    }
    __syncthreads();

    // --- staged writeback: out[((n*CH + c)*HO + ph)*WO + pw] ---
    float* outp = out + ((size_t)n * CH * HO + ph) * WO;
    for (int i = tid; i < CH * WO; i += 256) {
        const int c  = i / WO;
        const int pw = i - c * WO;
        outp[(size_t)c * (HO * WO) + pw] = s_out[pw][c];
    }
}

extern "C" void kernel_launch(void* const* d_in, const int* in_sizes, int n_in,
                              void* d_out, int out_size) {
    const float* features = (const float*)d_in[0];  // (1, 256, 200, 200)
    const float* rois     = (const float*)d_in[1];  // (512, 4)
    const float* img_size = (const float*)d_in[2];  // (2,)
    float* out = (float*)d_out;                     // (512, 256, 7, 7)

    const int n_rois = in_sizes[1] / 4;

    dim3 tgrid(HF * WF / 32, CH / 32);
    dim3 tblock(32, 8);
    transpose_kernel<<<tgrid, tblock>>>(features);

    dim3 rgrid(n_rois, HO);
    roialign_kernel<<<rgrid, 256>>>(rois, img_size, out);
}

// round 4
// speedup vs baseline: 1.5005x; 1.5005x over previous
#include <cuda_runtime.h>
#include <cuda_fp16.h>
#include <math.h>

#define HF 200
#define WF 200
#define CH 256
#define HO 7
#define WO 7
#define SUBS 2
#define HS (HO * SUBS)   // 14
#define WS (WO * SUBS)   // 14

#define ROW_BYTES (WF * CH * 2)   // 102400: byte stride of one feature row
#define COL_BYTES (CH * 2)        // 512:    byte stride of one feature col

// Channels-last fp16 scratch copy: g_featTh[(y*WF + x)*CH + c]  (20.5 MB)
__device__ __align__(16) __half g_featTh[HF * WF * CH];

static __device__ __forceinline__ __half2 u2h2(unsigned u) {
    return *reinterpret_cast<__half2*>(&u);
}

// ---------------------------------------------------------------------------
// Kernel 1: transpose (C, H*W) f32 -> (H*W, C) fp16 via 32x32 smem tiles
// (~7 TB/s, HBM-roofline bound: unchanged)
// ---------------------------------------------------------------------------
__global__ void transpose_kernel(const float* __restrict__ in) {
    __shared__ float tile[32][33];
    const int p0 = blockIdx.x * 32;
    const int c0 = blockIdx.y * 32;
    const int tx = threadIdx.x;
    const int ty = threadIdx.y;

#pragma unroll
    for (int i = 0; i < 32; i += 8) {
        tile[ty + i][tx] = in[(size_t)(c0 + ty + i) * (HF * WF) + (p0 + tx)];
    }
    __syncthreads();

    const int tid = ty * 32 + tx;
#pragma unroll
    for (int it = 0; it < 2; it++) {
        const int idx = tid + it * 256;
        const int p_local = idx >> 4;
        const int k = idx & 15;
        __half2 h = __floats2half2_rn(tile[2 * k][p_local], tile[2 * k + 1][p_local]);
        *(__half2*)&g_featTh[(size_t)(p0 + p_local) * CH + c0 + 2 * k] = h;
    }
}

// ---------------------------------------------------------------------------
// Kernel 2: ROI align + 2x2 max subsample.
// Grid: (N, HO). 256 threads; 224 active = 7 pw x 32 c8.
// Each thread computes its own 4 row-offsets x 4 col-offsets in registers,
// front-batches all 16 LDG.128 (MLP~16), then does the bilinear lerp + max
// entirely in half2. No shared memory in the hot path.
// ---------------------------------------------------------------------------
__global__ __launch_bounds__(256) void roialign_kernel(
    const float* __restrict__ rois,
    const float* __restrict__ img_size,
    float* __restrict__ out)
{
    const int n  = blockIdx.x;
    const int ph = blockIdx.y;
    const int tid = threadIdx.x;

    __shared__ float s_out[WO][CH + 4];

    // --- per-ROI geometry (scalar) ---
    const float4 roi = ((const float4*)rois)[n];
    const float Hi = img_size[0];
    const float Wi = img_size[1];
    const float sy_scale = (HF - 1.0f) / (Hi - 1.0f);
    const float sx_scale = (WF - 1.0f) / (Wi - 1.0f);
    const float r0 = roi.x * sy_scale;   // y1
    const float r1 = roi.y * sx_scale;   // x1
    const float h_step = (roi.z * sy_scale - r0) / (float)HS;
    const float w_step = (roi.w * sx_scale - r1) / (float)WS;

    if (tid < WO * (CH / 8)) {
        const int pw = tid >> 5;
        const int c8 = tid & 31;

        // --- per-thread sample coordinates (registers only) ---
        const float yy0 = ((float)(ph * SUBS) + 0.5f) * h_step + r0;
        const float yy1 = ((float)(ph * SUBS + 1) + 0.5f) * h_step + r0;
        const float yf0 = floorf(yy0), yf1 = floorf(yy1);
        const float xx0 = ((float)(pw * SUBS) + 0.5f) * w_step + r1;
        const float xx1 = ((float)(pw * SUBS + 1) + 0.5f) * w_step + r1;
        const float xf0 = floorf(xx0), xf1 = floorf(xx1);

        const __half2 fy0 = __float2half2_rn(yy0 - yf0);
        const __half2 fy1 = __float2half2_rn(yy1 - yf1);
        const __half2 fx0 = __float2half2_rn(xx0 - xf0);
        const __half2 fx1 = __float2half2_rn(xx1 - xf1);

        // 4 row byte-offsets x 4 col byte-offsets
        const unsigned ru0 = (unsigned)((int)yf0)        * ROW_BYTES;
        const unsigned rd0 = (unsigned)((int)ceilf(yy0)) * ROW_BYTES;
        const unsigned ru1 = (unsigned)((int)yf1)        * ROW_BYTES;
        const unsigned rd1 = (unsigned)((int)ceilf(yy1)) * ROW_BYTES;
        const unsigned cl0 = (unsigned)((int)xf0)        * COL_BYTES;
        const unsigned cr0 = (unsigned)((int)ceilf(xx0)) * COL_BYTES;
        const unsigned cl1 = (unsigned)((int)xf1)        * COL_BYTES;
        const unsigned cr1 = (unsigned)((int)ceilf(xx1)) * COL_BYTES;

        const char* fb = (const char*)g_featTh + c8 * 16;

        // --- front-batch all 16 corner loads ---
        uint4 v[16];
        // sample (sy=0, sx=0): rows u0/d0, cols l0/r0
        v[ 0] = *(const uint4*)(fb + (ru0 + cl0));
        v[ 1] = *(const uint4*)(fb + (ru0 + cr0));
        v[ 2] = *(const uint4*)(fb + (rd0 + cl0));
        v[ 3] = *(const uint4*)(fb + (rd0 + cr0));
        // (sy=0, sx=1)
        v[ 4] = *(const uint4*)(fb + (ru0 + cl1));
        v[ 5] = *(const uint4*)(fb + (ru0 + cr1));
        v[ 6] = *(const uint4*)(fb + (rd0 + cl1));
        v[ 7] = *(const uint4*)(fb + (rd0 + cr1));
        // (sy=1, sx=0)
        v[ 8] = *(const uint4*)(fb + (ru1 + cl0));
        v[ 9] = *(const uint4*)(fb + (ru1 + cr0));
        v[10] = *(const uint4*)(fb + (rd1 + cl0));
        v[11] = *(const uint4*)(fb + (rd1 + cr0));
        // (sy=1, sx=1)
        v[12] = *(const uint4*)(fb + (ru1 + cl1));
        v[13] = *(const uint4*)(fb + (ru1 + cr1));
        v[14] = *(const uint4*)(fb + (rd1 + cl1));
        v[15] = *(const uint4*)(fb + (rd1 + cr1));

        __half2 best[4];
        const __half2 ninf = __float2half2_rn(-60000.0f);
#pragma unroll
        for (int j = 0; j < 4; j++) best[j] = ninf;

        const __half2 fxs[4] = {fx0, fx1, fx0, fx1};
        const __half2 fys[4] = {fy0, fy0, fy1, fy1};

#pragma unroll
        for (int s = 0; s < 4; s++) {
            const unsigned* pul = (const unsigned*)&v[s * 4 + 0];
            const unsigned* pur = (const unsigned*)&v[s * 4 + 1];
            const unsigned* pdl = (const unsigned*)&v[s * 4 + 2];
            const unsigned* pdr = (const unsigned*)&v[s * 4 + 3];
            const __half2 fx2 = fxs[s];
            const __half2 fy2 = fys[s];
#pragma unroll
            for (int j = 0; j < 4; j++) {
                const __half2 ul = u2h2(pul[j]);
                const __half2 ur = u2h2(pur[j]);
                const __half2 dl = u2h2(pdl[j]);
                const __half2 dr = u2h2(pdr[j]);
                const __half2 t = __hfma2(fx2, __hsub2(ur, ul), ul);
                const __half2 b = __hfma2(fx2, __hsub2(dr, dl), dl);
                const __half2 vv = __hfma2(fy2, __hsub2(b, t), t);
                best[j] = __hmax2(best[j], vv);
            }
        }

        const int c = c8 * 8;
#pragma unroll
        for (int j = 0; j < 4; j++) {
            const float2 f = __half22float2(best[j]);
            s_out[pw][c + 2 * j + 0] = f.x;
            s_out[pw][c + 2 * j + 1] = f.y;
        }
    }
    __syncthreads();

    // --- staged writeback: out[((n*CH + c)*HO + ph)*WO + pw] ---
    float* outp = out + ((size_t)n * CH * HO + ph) * WO;
    for (int i = tid; i < CH * WO; i += 256) {
        const int c  = i / WO;
        const int pw = i - c * WO;
        outp[(size_t)c * (HO * WO) + pw] = s_out[pw][c];
    }
}

extern "C" void kernel_launch(void* const* d_in, const int* in_sizes, int n_in,
                              void* d_out, int out_size) {
    const float* features = (const float*)d_in[0];  // (1, 256, 200, 200)
    const float* rois     = (const float*)d_in[1];  // (512, 4)
    const float* img_size = (const float*)d_in[2];  // (2,)
    float* out = (float*)d_out;                     // (512, 256, 7, 7)

    const int n_rois = in_sizes[1] / 4;

    dim3 tgrid(HF * WF / 32, CH / 32);
    dim3 tblock(32, 8);
    transpose_kernel<<<tgrid, tblock>>>(features);

    dim3 rgrid(n_rois, HO);
    roialign_kernel<<<rgrid, 256>>>(rois, img_size, out);
}

// round 5
// speedup vs baseline: 1.5843x; 1.0559x over previous
#include <cuda_runtime.h>
#include <cuda_fp16.h>
#include <math.h>

#define HF 200
#define WF 200
#define CH 256
#define HO 7
#define WO 7
#define SUBS 2
#define HS (HO * SUBS)   // 14
#define WS (WO * SUBS)   // 14

#define ROW_BYTES (WF * CH * 2)   // 102400
#define COL_BYTES (CH * 2)        // 512

// Channels-last fp16 scratch copy: g_featTh[(y*WF + x)*CH + c]  (20.5 MB)
__device__ __align__(16) __half g_featTh[HF * WF * CH];

static __device__ __forceinline__ __half2 u2h2(unsigned u) {
    return *reinterpret_cast<__half2*>(&u);
}

// ---------------------------------------------------------------------------
// Kernel 1: transpose (C, H*W) f32 -> (H*W, C) fp16 (HBM-roofline bound)
// ---------------------------------------------------------------------------
__global__ void transpose_kernel(const float* __restrict__ in) {
    __shared__ float tile[32][33];
    const int p0 = blockIdx.x * 32;
    const int c0 = blockIdx.y * 32;
    const int tx = threadIdx.x;
    const int ty = threadIdx.y;

#pragma unroll
    for (int i = 0; i < 32; i += 8) {
        tile[ty + i][tx] = in[(size_t)(c0 + ty + i) * (HF * WF) + (p0 + tx)];
    }
    __syncthreads();

    const int tid = ty * 32 + tx;
#pragma unroll
    for (int it = 0; it < 2; it++) {
        const int idx = tid + it * 256;
        const int p_local = idx >> 4;
        const int k = idx & 15;
        __half2 h = __floats2half2_rn(tile[2 * k][p_local], tile[2 * k + 1][p_local]);
        *(__half2*)&g_featTh[(size_t)(p0 + p_local) * CH + c0 + 2 * k] = h;
    }
}

// ---------------------------------------------------------------------------
// Kernel 2: ROI align + 2x2 max subsample.
// Grid: (N, HO). 256 threads; 224 active = 7 pw x 32 c8.
// ceil replaced by floor+1 (weight-0 when exact integer; always in bounds
// because samples are strictly inside [0, 199)). Writeback is incremental:
// no div/mod in the loop.
// ---------------------------------------------------------------------------
__global__ __launch_bounds__(256) void roialign_kernel(
    const float* __restrict__ rois,
    const float* __restrict__ img_size,
    float* __restrict__ out)
{
    const int n  = blockIdx.x;
    const int ph = blockIdx.y;
    const int tid = threadIdx.x;

    __shared__ float s_out[WO][CH + 4];   // pitch 260 floats

    const float4 roi = ((const float4*)rois)[n];
    const float Hi = img_size[0];
    const float Wi = img_size[1];
    const float sy_scale = (HF - 1.0f) / (Hi - 1.0f);
    const float sx_scale = (WF - 1.0f) / (Wi - 1.0f);
    const float r0 = roi.x * sy_scale;
    const float r1 = roi.y * sx_scale;
    const float h_step = (roi.z * sy_scale - r0) / (float)HS;
    const float w_step = (roi.w * sx_scale - r1) / (float)WS;

    if (tid < WO * (CH / 8)) {
        const int pw = tid >> 5;
        const int c8 = tid & 31;

        // sample coords (2 rows for this ph, 2 cols for this pw)
        const float yy0 = ((float)(2 * ph) + 0.5f) * h_step + r0;
        const float yy1 = yy0 + h_step;
        const float xx0 = ((float)(2 * pw) + 0.5f) * w_step + r1;
        const float xx1 = xx0 + w_step;

        const int iy0 = __float2int_rd(yy0);
        const int iy1 = __float2int_rd(yy1);
        const int ix0 = __float2int_rd(xx0);
        const int ix1 = __float2int_rd(xx1);

        const __half2 fy0 = __float2half2_rn(yy0 - (float)iy0);
        const __half2 fy1 = __float2half2_rn(yy1 - (float)iy1);
        const __half2 fx0 = __float2half2_rn(xx0 - (float)ix0);
        const __half2 fx1 = __float2half2_rn(xx1 - (float)ix1);

        // row/col byte offsets; "down"/"right" = +1 stride (floor+1 trick)
        const unsigned ru0 = (unsigned)iy0 * ROW_BYTES;
        const unsigned ru1 = (unsigned)iy1 * ROW_BYTES;
        const unsigned rd0 = ru0 + ROW_BYTES;
        const unsigned rd1 = ru1 + ROW_BYTES;
        const unsigned cl0 = (unsigned)ix0 * COL_BYTES;
        const unsigned cl1 = (unsigned)ix1 * COL_BYTES;
        const unsigned cr0 = cl0 + COL_BYTES;
        const unsigned cr1 = cl1 + COL_BYTES;

        const char* fb = (const char*)g_featTh + c8 * 16;

        uint4 v[16];
        v[ 0] = *(const uint4*)(fb + (ru0 + cl0));
        v[ 1] = *(const uint4*)(fb + (ru0 + cr0));
        v[ 2] = *(const uint4*)(fb + (rd0 + cl0));
        v[ 3] = *(const uint4*)(fb + (rd0 + cr0));
        v[ 4] = *(const uint4*)(fb + (ru0 + cl1));
        v[ 5] = *(const uint4*)(fb + (ru0 + cr1));
        v[ 6] = *(const uint4*)(fb + (rd0 + cl1));
        v[ 7] = *(const uint4*)(fb + (rd0 + cr1));
        v[ 8] = *(const uint4*)(fb + (ru1 + cl0));
        v[ 9] = *(const uint4*)(fb + (ru1 + cr0));
        v[10] = *(const uint4*)(fb + (rd1 + cl0));
        v[11] = *(const uint4*)(fb + (rd1 + cr0));
        v[12] = *(const uint4*)(fb + (ru1 + cl1));
        v[13] = *(const uint4*)(fb + (ru1 + cr1));
        v[14] = *(const uint4*)(fb + (rd1 + cl1));
        v[15] = *(const uint4*)(fb + (rd1 + cr1));

        __half2 best[4];
        const __half2 ninf = __float2half2_rn(-60000.0f);
#pragma unroll
        for (int j = 0; j < 4; j++) best[j] = ninf;

        const __half2 fxs[4] = {fx0, fx1, fx0, fx1};
        const __half2 fys[4] = {fy0, fy0, fy1, fy1};

#pragma unroll
        for (int s = 0; s < 4; s++) {
            const unsigned* pul = (const unsigned*)&v[s * 4 + 0];
            const unsigned* pur = (const unsigned*)&v[s * 4 + 1];
            const unsigned* pdl = (const unsigned*)&v[s * 4 + 2];
            const unsigned* pdr = (const unsigned*)&v[s * 4 + 3];
            const __half2 fx2 = fxs[s];
            const __half2 fy2 = fys[s];
#pragma unroll
            for (int j = 0; j < 4; j++) {
                const __half2 ul = u2h2(pul[j]);
                const __half2 ur = u2h2(pur[j]);
                const __half2 dl = u2h2(pdl[j]);
                const __half2 dr = u2h2(pdr[j]);
                const __half2 t = __hfma2(fx2, __hsub2(ur, ul), ul);
                const __half2 b = __hfma2(fx2, __hsub2(dr, dl), dl);
                const __half2 vv = __hfma2(fy2, __hsub2(b, t), t);
                best[j] = __hmax2(best[j], vv);
            }
        }

        const int c = c8 * 8;
#pragma unroll
        for (int j = 0; j < 4; j++) {
            const float2 f = __half22float2(best[j]);
            s_out[pw][c + 2 * j + 0] = f.x;
            s_out[pw][c + 2 * j + 1] = f.y;
        }
    }
    __syncthreads();

    // --- incremental writeback: 1792 floats, 7 iters/thread, no div in loop
    // out index for (c, pw) = n*CH*49 + c*49 + ph*7 + pw
    {
        int c  = tid / 7;        // one div+mod at entry (magic-mul)
        int pw = tid - c * 7;
        const float* srow = &s_out[0][0];
        int sidx = pw * (CH + 4) + c;
        float* gp = out + (size_t)n * (CH * HO * WO) + ph * WO + c * (HO * WO) + pw;

        // step per iter: i += 256  ->  c += 36, pw += 4 (wrap: c += 1, pw -= 7)
#pragma unroll
        for (int k = 0; k < 7; k++) {
            *gp = srow[sidx];
            pw   += 4;
            sidx += 4 * (CH + 4) + 36;        // +1076
            gp   += 36 * (HO * WO) + 4;       // +1768
            if (pw >= 7) {
                pw   -= 7;
                sidx -= 7 * (CH + 4) - 1;     // -1819
                gp   += (HO * WO) - 7;        // +42
            }
        }
    }
}

extern "C" void kernel_launch(void* const* d_in, const int* in_sizes, int n_in,
                              void* d_out, int out_size) {
    const float* features = (const float*)d_in[0];  // (1, 256, 200, 200)
    const float* rois     = (const float*)d_in[1];  // (512, 4)
    const float* img_size = (const float*)d_in[2];  // (2,)
    float* out = (float*)d_out;                     // (512, 256, 7, 7)

    const int n_rois = in_sizes[1] / 4;

    dim3 tgrid(HF * WF / 32, CH / 32);
    dim3 tblock(32, 8);
    transpose_kernel<<<tgrid, tblock>>>(features);

    dim3 rgrid(n_rois, HO);
    roialign_kernel<<<rgrid, 256>>>(rois, img_size, out);
}